// round 6
// baseline (speedup 1.0000x reference)
#include <cuda_runtime.h>
#include <cstdint>

#define B_SZ    2
#define S_LEN   2048
#define D_MODEL 1024
#define NHEADS  16
#define DK      64
#define M_ROWS  (B_SZ * S_LEN)     // 4096
#define QKV_N   (3 * D_MODEL)      // 3072

// Scratch (alloc-free: __device__ globals)
__device__ float g_qkv[(size_t)M_ROWS * QKV_N];   // rounded qkv
__device__ float g_ctx[(size_t)M_ROWS * D_MODEL]; // rounded ctx
__device__ float g_xr [(size_t)M_ROWS * D_MODEL];         // rounded x
__device__ float g_wqr[(size_t)D_MODEL * QKV_N];          // rounded W_qkv
__device__ float g_wor[(size_t)D_MODEL * D_MODEL];        // rounded W_o

// ---------------------------------------------------------------------------
// helpers
// ---------------------------------------------------------------------------
__device__ __forceinline__ float f2tf_f(float f) {
    unsigned u;
    asm("cvt.rna.tf32.f32 %0, %1;" : "=r"(u) : "f"(f));
    return __uint_as_float(u);
}
__device__ __forceinline__ unsigned f2tf(float f) {
    unsigned u;
    asm("cvt.rna.tf32.f32 %0, %1;" : "=r"(u) : "f"(f));
    return u;
}
__device__ __forceinline__ uint32_t smem_u32(const void* p) {
    uint32_t a;
    asm("{ .reg .u64 t; cvta.to.shared.u64 t, %1; cvt.u32.u64 %0, t; }"
        : "=r"(a) : "l"(p));
    return a;
}

#define CP_ASYNC16(dst, src) \
    asm volatile("cp.async.cg.shared.global [%0], [%1], 16;" :: "r"(dst), "l"(src))
#define CP_COMMIT() asm volatile("cp.async.commit_group;" ::: "memory")
#define CP_WAIT1()  asm volatile("cp.async.wait_group 1;" ::: "memory")
#define CP_WAIT0()  asm volatile("cp.async.wait_group 0;" ::: "memory")

__device__ __forceinline__ void mma_tf32(float* c, const unsigned* a,
                                         unsigned b0, unsigned b1) {
    asm volatile(
        "mma.sync.aligned.m16n8k8.row.col.f32.tf32.tf32.f32 "
        "{%0,%1,%2,%3}, {%4,%5,%6,%7}, {%8,%9}, {%0,%1,%2,%3};\n"
        : "+f"(c[0]), "+f"(c[1]), "+f"(c[2]), "+f"(c[3])
        : "r"(a[0]), "r"(a[1]), "r"(a[2]), "r"(a[3]), "r"(b0), "r"(b1));
}

// ---------------------------------------------------------------------------
// one-time RNA tf32 rounding (elementwise, float4)
// ---------------------------------------------------------------------------
__global__ void __launch_bounds__(256)
k_round4(const float* __restrict__ in, float* __restrict__ out, int n4)
{
    int i = blockIdx.x * 256 + threadIdx.x;
    if (i < n4) {
        float4 v = ((const float4*)in)[i];
        v.x = f2tf_f(v.x); v.y = f2tf_f(v.y);
        v.z = f2tf_f(v.z); v.w = f2tf_f(v.w);
        ((float4*)out)[i] = v;
    }
}

// ---------------------------------------------------------------------------
// TF32 GEMM, cp.async double-buffered. C[M,N] = A[M,K]@B[K,N] + bias.
// Block 128x128, BK=32, 256 threads = 8 warps (4 M x 2 N), warp tile 32x64.
// Inputs must already be tf32-rounded. ROUND: round outputs (for g_qkv/g_ctx
// producers) or leave fp32 (final output).
// Padded strides: As 36 (=4 mod 32), Bs 136 (=8 mod 32); rows 16B-aligned.
// ---------------------------------------------------------------------------
#define AS_STR 36
#define BS_STR 136
#define ABUF(i) ((i) * 128 * AS_STR)                 // words
#define BBUF(i) (2 * 128 * AS_STR + (i) * 32 * BS_STR)
#define GT_WORDS (2 * 128 * AS_STR + 2 * 32 * BS_STR) // 17920
#define GT_SMEM  (GT_WORDS * 4)                       // 71680 B

template <bool ROUND>
__global__ void __launch_bounds__(256, 1)
k_gemm(const float* __restrict__ A, const float* __restrict__ B,
       const float* __restrict__ bias, float* __restrict__ C,
       int N, int K)
{
    extern __shared__ unsigned smw[];
    const uint32_t sb = smem_u32(smw);
    const int tid  = threadIdx.x;
    const int wid  = tid >> 5;
    const int lane = tid & 31;
    const int lr   = lane >> 2;
    const int lc   = lane & 3;
    const int wm   = (wid & 3) * 32;
    const int wn   = (wid >> 2) * 64;
    const int bm   = blockIdx.y * 128;
    const int bn   = blockIdx.x * 128;

    float acc[2][8][4];
    #pragma unroll
    for (int i = 0; i < 2; i++)
        #pragma unroll
        for (int j = 0; j < 8; j++)
            #pragma unroll
            for (int q = 0; q < 4; q++) acc[i][j][q] = 0.f;

    auto issue = [&](int t) {
        const int buf = t & 1;
        const int k0  = t * 32;
        #pragma unroll
        for (int it = 0; it < 4; it++) {          // A: 128 rows x 8 chunks
            const int f = tid + 256 * it;
            const int m = f >> 3, c = f & 7;
            CP_ASYNC16(sb + (ABUF(buf) + m * AS_STR + 4 * c) * 4,
                       A + (size_t)(bm + m) * K + k0 + 4 * c);
        }
        #pragma unroll
        for (int it = 0; it < 4; it++) {          // B: 32 rows x 32 chunks
            const int f = tid + 256 * it;
            const int k = f >> 5, c = f & 31;
            CP_ASYNC16(sb + (BBUF(buf) + k * BS_STR + 4 * c) * 4,
                       B + (size_t)(k0 + k) * N + bn + 4 * c);
        }
    };

    const int nT = K / 32;
    issue(0); CP_COMMIT();

    for (int t = 0; t < nT; t++) {
        const int buf = t & 1;
        const bool more = (t + 1 < nT);
        if (more) { issue(t + 1); CP_COMMIT(); CP_WAIT1(); }
        else      { CP_WAIT0(); }
        __syncthreads();

        const unsigned* As_ = smw + ABUF(buf);
        const unsigned* Bs_ = smw + BBUF(buf);
        #pragma unroll
        for (int kk = 0; kk < 4; kk++) {
            unsigned af[2][4];
            #pragma unroll
            for (int i = 0; i < 2; i++) {
                const int m = wm + 16 * i + lr;
                af[i][0] = As_[m * AS_STR + 8 * kk + lc];
                af[i][1] = As_[(m + 8) * AS_STR + 8 * kk + lc];
                af[i][2] = As_[m * AS_STR + 8 * kk + lc + 4];
                af[i][3] = As_[(m + 8) * AS_STR + 8 * kk + lc + 4];
            }
            #pragma unroll
            for (int j = 0; j < 8; j++) {
                const unsigned b0 = Bs_[(8 * kk + lc) * BS_STR + wn + 8 * j + lr];
                const unsigned b1 = Bs_[(8 * kk + lc + 4) * BS_STR + wn + 8 * j + lr];
                mma_tf32(acc[0][j], af[0], b0, b1);
                mma_tf32(acc[1][j], af[1], b0, b1);
            }
        }
        __syncthreads();
    }

    #pragma unroll
    for (int j = 0; j < 8; j++) {
        const int col = bn + wn + 8 * j + 2 * lc;
        const float bs0 = bias[col], bs1 = bias[col + 1];
        #pragma unroll
        for (int i = 0; i < 2; i++) {
            const int row = bm + wm + 16 * i + lr;
            float2 r0, r1;
            if (ROUND) {
                r0 = make_float2(f2tf_f(acc[i][j][0] + bs0), f2tf_f(acc[i][j][1] + bs1));
                r1 = make_float2(f2tf_f(acc[i][j][2] + bs0), f2tf_f(acc[i][j][3] + bs1));
            } else {
                r0 = make_float2(acc[i][j][0] + bs0, acc[i][j][1] + bs1);
                r1 = make_float2(acc[i][j][2] + bs0, acc[i][j][3] + bs1);
            }
            *(float2*)(C + (size_t)row * N + col) = r0;
            *(float2*)(C + (size_t)(row + 8) * N + col) = r1;
        }
    }
}

// ---------------------------------------------------------------------------
// Flash attention, tf32 mma.sync, cp.async double-buffered K/V.
// Block = 256 threads (8 warps) = 128 query rows; 64-key tiles.
// g_qkv is pre-rounded, so K/V/Q need no cvt; P rounded in-register.
// Strides: K 68 (=4 mod 32), V 72 (=8 mod 32), P 68; rows 16B-aligned.
// ---------------------------------------------------------------------------
#define KS_STR 68
#define VS_STR 72
#define PS_STR 68
#define K_OFF(i) ((i) * 64 * KS_STR)
#define V_OFF(i) (2 * 64 * KS_STR + (i) * 64 * VS_STR)
#define P_OFF    (2 * 64 * KS_STR + 2 * 64 * VS_STR)     // 17920
#define AT_WORDS (P_OFF + 128 * PS_STR)                  // 26624
#define AT_SMEM  (AT_WORDS * 4)                          // 106496 B

__global__ void __launch_bounds__(256, 1)
k_attn()
{
    extern __shared__ unsigned smw[];
    const uint32_t sb = smem_u32(smw);
    const int tid  = threadIdx.x;
    const int wid  = tid >> 5;
    const int lane = tid & 31;
    const int lr   = lane >> 2;
    const int lc   = lane & 3;
    const int bh   = blockIdx.x;
    const int b    = bh >> 4;
    const int h    = bh & 15;
    const int q0   = blockIdx.y * 128;

    const float* base = g_qkv + (size_t)b * S_LEN * QKV_N;
    const int ho = h * (3 * DK);

    // Q fragments (pre-rounded in g_qkv; x0.125 is exact)
    unsigned Qf[8][4];
    {
        const float* qr0 = base + (size_t)(q0 + wid * 16 + lr) * QKV_N + ho;
        const float* qr1 = qr0 + (size_t)8 * QKV_N;
        #pragma unroll
        for (int kk = 0; kk < 8; kk++) {
            Qf[kk][0] = __float_as_uint(0.125f * qr0[8 * kk + lc]);
            Qf[kk][1] = __float_as_uint(0.125f * qr1[8 * kk + lc]);
            Qf[kk][2] = __float_as_uint(0.125f * qr0[8 * kk + lc + 4]);
            Qf[kk][3] = __float_as_uint(0.125f * qr1[8 * kk + lc + 4]);
        }
    }

    auto issue = [&](int t) {
        const int buf = t & 1;
        const float* kb = base + (size_t)(t * 64) * QKV_N + ho + DK;
        #pragma unroll
        for (int it = 0; it < 8; it++) {          // it<4: K rows, it>=4: V rows
            const int f = tid + 256 * it;
            const int r = (f >> 4) & 63;
            const int c = f & 15;
            if (it < 4)
                CP_ASYNC16(sb + (K_OFF(buf) + r * KS_STR + 4 * c) * 4,
                           kb + (size_t)r * QKV_N + 4 * c);
            else
                CP_ASYNC16(sb + (V_OFF(buf) + r * VS_STR + 4 * c) * 4,
                           kb + (size_t)r * QKV_N + DK + 4 * c);
        }
    };

    float oAcc[8][4];
    #pragma unroll
    for (int j = 0; j < 8; j++)
        #pragma unroll
        for (int q = 0; q < 4; q++) oAcc[j][q] = 0.f;
    float m0 = -1e30f, m1 = -1e30f, l0 = 0.f, l1 = 0.f;

    unsigned* Ps = smw + P_OFF;
    const int pr0 = (wid * 16 + lr) * PS_STR;
    const int pr1 = pr0 + 8 * PS_STR;

    const int nT = S_LEN / 64;
    issue(0); CP_COMMIT();

    for (int t = 0; t < nT; t++) {
        const int buf = t & 1;
        const bool more = (t + 1 < nT);
        if (more) { issue(t + 1); CP_COMMIT(); CP_WAIT1(); }
        else      { CP_WAIT0(); }
        __syncthreads();

        const unsigned* Ks_ = smw + K_OFF(buf);
        const unsigned* Vs_ = smw + V_OFF(buf);

        // S = Q @ K^T
        float sAcc[8][4];
        #pragma unroll
        for (int j = 0; j < 8; j++) {
            sAcc[j][0] = sAcc[j][1] = sAcc[j][2] = sAcc[j][3] = 0.f;
            #pragma unroll
            for (int kk = 0; kk < 8; kk++) {
                const unsigned b0 = Ks_[(8 * j + lr) * KS_STR + 8 * kk + lc];
                const unsigned b1 = Ks_[(8 * j + lr) * KS_STR + 8 * kk + lc + 4];
                mma_tf32(sAcc[j], Qf[kk], b0, b1);
            }
        }

        // online softmax
        float mx0 = -1e30f, mx1 = -1e30f;
        #pragma unroll
        for (int j = 0; j < 8; j++) {
            mx0 = fmaxf(mx0, fmaxf(sAcc[j][0], sAcc[j][1]));
            mx1 = fmaxf(mx1, fmaxf(sAcc[j][2], sAcc[j][3]));
        }
        mx0 = fmaxf(mx0, __shfl_xor_sync(0xffffffffu, mx0, 1));
        mx0 = fmaxf(mx0, __shfl_xor_sync(0xffffffffu, mx0, 2));
        mx1 = fmaxf(mx1, __shfl_xor_sync(0xffffffffu, mx1, 1));
        mx1 = fmaxf(mx1, __shfl_xor_sync(0xffffffffu, mx1, 2));

        const float mn0 = fmaxf(m0, mx0), mn1 = fmaxf(m1, mx1);
        const float cor0 = __expf(m0 - mn0), cor1 = __expf(m1 - mn1);
        m0 = mn0; m1 = mn1;

        float s0 = 0.f, s1 = 0.f;
        #pragma unroll
        for (int j = 0; j < 8; j++) {
            sAcc[j][0] = __expf(sAcc[j][0] - mn0); s0 += sAcc[j][0];
            sAcc[j][1] = __expf(sAcc[j][1] - mn0); s0 += sAcc[j][1];
            sAcc[j][2] = __expf(sAcc[j][2] - mn1); s1 += sAcc[j][2];
            sAcc[j][3] = __expf(sAcc[j][3] - mn1); s1 += sAcc[j][3];
        }
        s0 += __shfl_xor_sync(0xffffffffu, s0, 1);
        s0 += __shfl_xor_sync(0xffffffffu, s0, 2);
        s1 += __shfl_xor_sync(0xffffffffu, s1, 1);
        s1 += __shfl_xor_sync(0xffffffffu, s1, 2);
        l0 = l0 * cor0 + s0;
        l1 = l1 * cor1 + s1;

        #pragma unroll
        for (int j = 0; j < 8; j++) {
            oAcc[j][0] *= cor0; oAcc[j][1] *= cor0;
            oAcc[j][2] *= cor1; oAcc[j][3] *= cor1;
        }

        // P -> smem (warp-private rows, rounded)
        #pragma unroll
        for (int j = 0; j < 8; j++) {
            const int colo = 8 * j + 2 * lc;
            *(uint2*)(Ps + pr0 + colo) = make_uint2(f2tf(sAcc[j][0]), f2tf(sAcc[j][1]));
            *(uint2*)(Ps + pr1 + colo) = make_uint2(f2tf(sAcc[j][2]), f2tf(sAcc[j][3]));
        }
        __syncwarp();

        // O += P @ V
        #pragma unroll
        for (int kk = 0; kk < 8; kk++) {
            unsigned pf[4];
            pf[0] = Ps[pr0 + 8 * kk + lc];
            pf[1] = Ps[pr1 + 8 * kk + lc];
            pf[2] = Ps[pr0 + 8 * kk + lc + 4];
            pf[3] = Ps[pr1 + 8 * kk + lc + 4];
            #pragma unroll
            for (int j = 0; j < 8; j++) {
                const unsigned b0 = Vs_[(8 * kk + lc) * VS_STR + 8 * j + lr];
                const unsigned b1 = Vs_[(8 * kk + lc + 4) * VS_STR + 8 * j + lr];
                mma_tf32(oAcc[j], pf, b0, b1);
            }
        }
    }

    // epilogue: normalize, round, store head-interleaved ctx
    const float inv0 = 1.f / l0, inv1 = 1.f / l1;
    float* orow0 = g_ctx + (size_t)(b * S_LEN + q0 + wid * 16 + lr) * D_MODEL + h * DK;
    float* orow1 = orow0 + (size_t)8 * D_MODEL;
    #pragma unroll
    for (int j = 0; j < 8; j++) {
        const int colo = 8 * j + 2 * lc;
        *(float2*)(orow0 + colo) =
            make_float2(f2tf_f(oAcc[j][0] * inv0), f2tf_f(oAcc[j][1] * inv0));
        *(float2*)(orow1 + colo) =
            make_float2(f2tf_f(oAcc[j][2] * inv1), f2tf_f(oAcc[j][3] * inv1));
    }
}

// ---------------------------------------------------------------------------
extern "C" void kernel_launch(void* const* d_in, const int* in_sizes, int n_in,
                              void* d_out, int out_size)
{
    (void)in_sizes; (void)n_in; (void)out_size;
    const float* x     = (const float*)d_in[0];
    const float* W_qkv = (const float*)d_in[1];
    const float* b_qkv = (const float*)d_in[2];
    const float* W_o   = (const float*)d_in[3];
    const float* b_o   = (const float*)d_in[4];
    float* out = (float*)d_out;

    static float *p_qkv = nullptr, *p_ctx, *p_xr, *p_wqr, *p_wor;
    if (!p_qkv) {
        cudaGetSymbolAddress((void**)&p_qkv, g_qkv);
        cudaGetSymbolAddress((void**)&p_ctx, g_ctx);
        cudaGetSymbolAddress((void**)&p_xr,  g_xr);
        cudaGetSymbolAddress((void**)&p_wqr, g_wqr);
        cudaGetSymbolAddress((void**)&p_wor, g_wor);
        cudaFuncSetAttribute(k_gemm<true>,
                             cudaFuncAttributeMaxDynamicSharedMemorySize, GT_SMEM);
        cudaFuncSetAttribute(k_gemm<false>,
                             cudaFuncAttributeMaxDynamicSharedMemorySize, GT_SMEM);
        cudaFuncSetAttribute(k_attn,
                             cudaFuncAttributeMaxDynamicSharedMemorySize, AT_SMEM);
    }

    // one-time RNA tf32 rounding of inputs/weights
    k_round4<<<(M_ROWS * D_MODEL / 4 + 255) / 256, 256>>>(x, p_xr, M_ROWS * D_MODEL / 4);
    k_round4<<<(D_MODEL * QKV_N / 4 + 255) / 256, 256>>>(W_qkv, p_wqr, D_MODEL * QKV_N / 4);
    k_round4<<<(D_MODEL * D_MODEL / 4 + 255) / 256, 256>>>(W_o, p_wor, D_MODEL * D_MODEL / 4);

    k_gemm<true><<<dim3(QKV_N / 128, M_ROWS / 128), 256, GT_SMEM>>>(
        p_xr, p_wqr, b_qkv, p_qkv, QKV_N, D_MODEL);
    k_attn<<<dim3(B_SZ * NHEADS, S_LEN / 128), 256, AT_SMEM>>>();
    k_gemm<false><<<dim3(D_MODEL / 128, M_ROWS / 128), 256, GT_SMEM>>>(
        p_ctx, p_wor, b_o, out, D_MODEL, D_MODEL);
}